// round 10
// baseline (speedup 1.0000x reference)
#include <cuda_runtime.h>
#include <cuda_fp16.h>
#include <cstdint>

#define N_NODES 100000
#define N_EDGES 1600000
#define D 128
#define N_PAD 102400   // 1024*100, padded so the scan needs no guards

// Scratch (no cudaMalloc allowed)
__device__ __align__(16) __half2 g_h[(size_t)N_NODES * (D / 2)];  // dis-premult feats, fp16
__device__ __align__(16) int   g_deg[N_NODES];
__device__ __align__(16) float g_dis[N_NODES];
__device__ __align__(16) int   g_cnt[N_PAD];
__device__ __align__(16) int   g_off[N_PAD + 4];
__device__ __align__(16) int   g_cursor[N_PAD];
__device__ __align__(16) int   g_bucket[N_EDGES];

// ---------------- zero counters ----------------
__global__ __launch_bounds__(256) void zero_kernel()
{
    int i = blockIdx.x * 256 + threadIdx.x;
    if (i < N_PAD) g_cnt[i] = 0;
    if (i < N_NODES) g_deg[i] = 0;
}

// ---------------- fused histogram: deg over src, cnt over dst --------------
__global__ __launch_bounds__(256) void hist_kernel(const int* __restrict__ ei)
{
    int e = blockIdx.x * 256 + threadIdx.x;
    if (e < N_EDGES) {
        atomicAdd(&g_deg[ei[e]], 1);
        atomicAdd(&g_cnt[ei[N_EDGES + e]], 1);
    }
}

// ---------------- tf32 helpers ----------------
__device__ __forceinline__ unsigned f2tf32(float f) {
    unsigned u;
    asm("cvt.rna.tf32.f32 %0, %1;" : "=r"(u) : "f"(f));
    return u;
}
__device__ __forceinline__ void mma_tf32(
    float& d0, float& d1, float& d2, float& d3,
    unsigned a0, unsigned a1, unsigned a2, unsigned a3,
    unsigned b0, unsigned b1)
{
    asm volatile(
        "mma.sync.aligned.m16n8k8.row.col.f32.tf32.tf32.f32 "
        "{%0,%1,%2,%3}, {%4,%5,%6,%7}, {%8,%9}, {%0,%1,%2,%3};"
        : "+f"(d0), "+f"(d1), "+f"(d2), "+f"(d3)
        : "r"(a0), "r"(a1), "r"(a2), "r"(a3), "r"(b0), "r"(b1));
}

// ---------------- GEMM via tf32 tensor cores --------------------------------
#define KC 64
#define XS(r, k) smem_u[(r) * 68 + (k)]
#define WS(n, k) smem_u[128 * 68 + (n) * 68 + (k)]

__global__ __launch_bounds__(256, 2) void gemm_mma_kernel(
    const float* __restrict__ x, const float* __restrict__ W,
    const float* __restrict__ b)
{
    extern __shared__ unsigned smem_u[];   // 2 * 128 * 68 * 4 = 69632 B

    const int tid  = threadIdx.x;
    const int lane = tid & 31;
    const int warp = tid >> 5;            // 0..7
    const int r    = lane >> 2;           // groupID 0..7
    const int c    = lane & 3;            // threadID-in-group 0..3
    const int lrow = warp * 16;
    const int m0   = blockIdx.x * 128;

    float acc[16][4];
#pragma unroll
    for (int t = 0; t < 16; t++)
#pragma unroll
        for (int j = 0; j < 4; j++) acc[t][j] = 0.f;

#pragma unroll
    for (int chunk = 0; chunk < 2; chunk++) {
        const int kc = chunk * KC;
#pragma unroll
        for (int i = 0; i < 8; i++) {
            int f = tid + i * 256;         // 0..2047
            int row = f >> 4;
            int kq  = f & 15;
            int grow = m0 + row;
            if (grow >= N_NODES) grow = N_NODES - 1;
            float4 xv = *reinterpret_cast<const float4*>(&x[(size_t)grow * D + kc + kq * 4]);
            uint4 xu = make_uint4(f2tf32(xv.x), f2tf32(xv.y), f2tf32(xv.z), f2tf32(xv.w));
            *reinterpret_cast<uint4*>(&XS(row, kq * 4)) = xu;
            float4 wv = *reinterpret_cast<const float4*>(&W[(size_t)row * D + kc + kq * 4]);
            uint4 wu = make_uint4(f2tf32(wv.x), f2tf32(wv.y), f2tf32(wv.z), f2tf32(wv.w));
            *reinterpret_cast<uint4*>(&WS(row, kq * 4)) = wu;
        }
        __syncthreads();

#pragma unroll
        for (int s = 0; s < 8; s++) {
            unsigned a0 = XS(lrow + r,     s * 8 + c);
            unsigned a1 = XS(lrow + r + 8, s * 8 + c);
            unsigned a2 = XS(lrow + r,     s * 8 + c + 4);
            unsigned a3 = XS(lrow + r + 8, s * 8 + c + 4);
#pragma unroll
            for (int t = 0; t < 16; t++) {
                unsigned b0 = WS(t * 8 + r, s * 8 + c);
                unsigned b1 = WS(t * 8 + r, s * 8 + c + 4);
                mma_tf32(acc[t][0], acc[t][1], acc[t][2], acc[t][3],
                         a0, a1, a2, a3, b0, b1);
            }
        }
        __syncthreads();
    }

    const int row_a = m0 + lrow + r;
    const int row_b = row_a + 8;
    const float dda = (row_a < N_NODES) ? g_dis[row_a] : 0.f;
    const float ddb = (row_b < N_NODES) ? g_dis[row_b] : 0.f;
#pragma unroll
    for (int t = 0; t < 16; t++) {
        int col0 = t * 8 + c * 2;
        float2 bias = *reinterpret_cast<const float2*>(&b[col0]);
        if (row_a < N_NODES) {
            g_h[(size_t)row_a * 64 + t * 4 + c] =
                __floats2half2_rn(dda * (acc[t][0] + bias.x),
                                  dda * (acc[t][1] + bias.y));
        }
        if (row_b < N_NODES) {
            g_h[(size_t)row_b * 64 + t * 4 + c] =
                __floats2half2_rn(ddb * (acc[t][2] + bias.x),
                                  ddb * (acc[t][3] + bias.y));
        }
    }
}

// ---------------- scan (+ fused dis) over g_cnt ------------------------------
// 1024 threads; thread tid owns int4 chunks tid*25..tid*25+24 (100 ints).
__global__ __launch_bounds__(1024) void scan_kernel()
{
    __shared__ int ssum[1024];
    const int tid = threadIdx.x;
    const int4* cnt4 = reinterpret_cast<const int4*>(g_cnt);

    // fused: dis = rsqrt(deg+1) over the same index range (25000 int4 total)
    const int4* deg4 = reinterpret_cast<const int4*>(g_deg);
    float4* dis4 = reinterpret_cast<float4*>(g_dis);
#pragma unroll
    for (int k = 0; k < 25; k++) {
        int gi = tid * 25 + k;
        if (gi < N_NODES / 4) {
            int4 dv = deg4[gi];
            float4 o;
            o.x = rsqrtf((float)(dv.x + 1));
            o.y = rsqrtf((float)(dv.y + 1));
            o.z = rsqrtf((float)(dv.z + 1));
            o.w = rsqrtf((float)(dv.w + 1));
            dis4[gi] = o;
        }
    }

    int s = 0;
#pragma unroll
    for (int k = 0; k < 25; k++) {
        int4 v = cnt4[tid * 25 + k];
        s += v.x + v.y + v.z + v.w;
    }
    ssum[tid] = s;
    __syncthreads();

    for (int d = 1; d < 1024; d <<= 1) {
        int v = (tid >= d) ? ssum[tid - d] : 0;
        __syncthreads();
        ssum[tid] += v;
        __syncthreads();
    }
    int running = (tid == 0) ? 0 : ssum[tid - 1];

    int4* off4 = reinterpret_cast<int4*>(g_off);
    int4* cur4 = reinterpret_cast<int4*>(g_cursor);
#pragma unroll
    for (int k = 0; k < 25; k++) {
        int4 cc = cnt4[tid * 25 + k];
        int4 o;
        o.x = running;              running += cc.x;
        o.y = running;              running += cc.y;
        o.z = running;              running += cc.z;
        o.w = running;              running += cc.w;
        off4[tid * 25 + k] = o;
        cur4[tid * 25 + k] = o;
    }
}

// ---------------- bucket fill: group src ids by dst -------------------------
__global__ __launch_bounds__(256) void fill_kernel(const int* __restrict__ ei)
{
    int e = blockIdx.x * 256 + threadIdx.x;
    if (e < N_EDGES) {
        int src = ei[e];
        int dst = ei[N_EDGES + e];
        int pos = atomicAdd(&g_cursor[dst], 1);
        g_bucket[pos] = src;
    }
}

// ---------------- gather: warp per node, 8 loads in flight per half-warp ----
#define ACC4(U) do {                                                          \
    float2 f_;                                                                \
    f_ = __half22float2(*reinterpret_cast<__half2*>(&(U).x)); a0.x += f_.x; a0.y += f_.y; \
    f_ = __half22float2(*reinterpret_cast<__half2*>(&(U).y)); a1.x += f_.x; a1.y += f_.y; \
    f_ = __half22float2(*reinterpret_cast<__half2*>(&(U).z)); a2.x += f_.x; a2.y += f_.y; \
    f_ = __half22float2(*reinterpret_cast<__half2*>(&(U).w)); a3.x += f_.x; a3.y += f_.y; \
} while (0)

__global__ __launch_bounds__(256) void gather_kernel(float* __restrict__ out)
{
    const int node = blockIdx.x * 8 + (threadIdx.x >> 5);
    if (node >= N_NODES) return;
    const int lane = threadIdx.x & 31;
    const int hf   = lane >> 4;      // 0/1 half-warp
    const int sub  = lane & 15;      // 16 lanes cover a 256B fp16 row
    const unsigned FULL = 0xffffffffu;

    const int start = g_off[node];
    const int end   = g_off[node + 1];
    const int cnt   = end - start;
    const float dd  = g_dis[node];
    const uint4* hbase = reinterpret_cast<const uint4*>(g_h);

    // coalesced index prefetch: lane L holds src id of edge L
    int idx = (lane < cnt) ? g_bucket[start + lane] : 0;

    float2 a0 = make_float2(0.f, 0.f), a1 = a0, a2 = a0, a3 = a0;

    // self-loop counted once (half 0)
    if (hf == 0) {
        uint4 u = hbase[(size_t)node * 16 + sub];
        a0 = __half22float2(*reinterpret_cast<__half2*>(&u.x));
        a1 = __half22float2(*reinterpret_cast<__half2*>(&u.y));
        a2 = __half22float2(*reinterpret_cast<__half2*>(&u.z));
        a3 = __half22float2(*reinterpret_cast<__half2*>(&u.w));
    }

    const int m = cnt < 32 ? cnt : 32;   // warp-uniform
    int base = 0;

    // batches of 16 edges: 8 independent LDG.128 in flight per half-warp
    for (; base + 16 <= m; base += 16) {
        int s[8];
#pragma unroll
        for (int q = 0; q < 8; q++)
            s[q] = __shfl_sync(FULL, idx, base + hf + 2 * q);
        uint4 u[8];
#pragma unroll
        for (int q = 0; q < 8; q++)
            u[q] = hbase[(size_t)s[q] * 16 + sub];
#pragma unroll
        for (int q = 0; q < 8; q++)
            ACC4(u[q]);
    }
    // batch of 8 (warp-uniform condition)
    if (m - base >= 8) {
        int s[4];
#pragma unroll
        for (int q = 0; q < 4; q++)
            s[q] = __shfl_sync(FULL, idx, base + hf + 2 * q);
        uint4 u[4];
#pragma unroll
        for (int q = 0; q < 4; q++)
            u[q] = hbase[(size_t)s[q] * 16 + sub];
#pragma unroll
        for (int q = 0; q < 4; q++)
            ACC4(u[q]);
        base += 8;
    }
    // remainder: uniform loop, shfl unconditional, load predicated
    for (int r = base; r < m; r += 2) {
        int ee = r + hf;
        int s0 = __shfl_sync(FULL, idx, ee & 31);
        if (ee < m) {
            uint4 u0 = hbase[(size_t)s0 * 16 + sub];
            ACC4(u0);
        }
    }
    // rare tail: degree > 32 (no warp collectives — divergence OK)
    for (int j = start + 32 + hf; j < end; j += 2) {
        int s0 = g_bucket[j];
        uint4 u0 = hbase[(size_t)s0 * 16 + sub];
        ACC4(u0);
    }

    // combine the two half-warps (lane pairs with lane^16, same features)
    a0.x += __shfl_xor_sync(FULL, a0.x, 16);
    a0.y += __shfl_xor_sync(FULL, a0.y, 16);
    a1.x += __shfl_xor_sync(FULL, a1.x, 16);
    a1.y += __shfl_xor_sync(FULL, a1.y, 16);
    a2.x += __shfl_xor_sync(FULL, a2.x, 16);
    a2.y += __shfl_xor_sync(FULL, a2.y, 16);
    a3.x += __shfl_xor_sync(FULL, a3.x, 16);
    a3.y += __shfl_xor_sync(FULL, a3.y, 16);

    const float coef = 0.125f;  // sqrt(2/128)
    float4 v;
    if (hf == 0) {
        v.x = a0.x; v.y = a0.y; v.z = a1.x; v.w = a1.y;
    } else {
        v.x = a2.x; v.y = a2.y; v.z = a3.x; v.w = a3.y;
    }
    v.x = coef * fmaxf(dd * v.x, 0.f);
    v.y = coef * fmaxf(dd * v.y, 0.f);
    v.z = coef * fmaxf(dd * v.z, 0.f);
    v.w = coef * fmaxf(dd * v.w, 0.f);
    *reinterpret_cast<float4*>(&out[(size_t)node * D + sub * 8 + hf * 4]) = v;
}

extern "C" void kernel_launch(void* const* d_in, const int* in_sizes, int n_in,
                              void* d_out, int out_size)
{
    const float* x  = (const float*)d_in[0];
    const int*   ei = (const int*)d_in[1];   // int32: JAX x64 disabled
    const float* W  = (const float*)d_in[2];
    const float* b  = (const float*)d_in[3];
    float* out = (float*)d_out;

    const int GEMM_SMEM = 2 * 128 * 68 * 4;  // 69632 B
    static bool attr_set = false;
    if (!attr_set) {
        cudaFuncSetAttribute(gemm_mma_kernel,
                             cudaFuncAttributeMaxDynamicSharedMemorySize, GEMM_SMEM);
        attr_set = true;
    }

    zero_kernel<<<(N_PAD + 255) / 256, 256>>>();
    hist_kernel<<<(N_EDGES + 255) / 256, 256>>>(ei);
    scan_kernel<<<1, 1024>>>();                    // also computes g_dis
    gemm_mma_kernel<<<(N_NODES + 127) / 128, 256, GEMM_SMEM>>>(x, W, b);
    fill_kernel<<<(N_EDGES + 255) / 256, 256>>>(ei);
    gather_kernel<<<(N_NODES + 7) / 8, 256>>>(out);
}

// round 11
// speedup vs baseline: 1.1056x; 1.1056x over previous
#include <cuda_runtime.h>
#include <cuda_fp16.h>
#include <cstdint>

#define N_NODES 100000
#define N_EDGES 1600000
#define D 128
#define N_PAD 102400   // 1024*100, padded so the scan needs no guards

// Scratch (no cudaMalloc allowed)
__device__ __align__(16) float   g_hraw[(size_t)N_NODES * D];     // xW^T+b, fp32 (51.2MB)
__device__ __align__(16) __half2 g_h[(size_t)N_NODES * (D / 2)];  // dis-premult, fp16 (25.6MB)
__device__ __align__(16) int   g_deg[N_NODES];
__device__ __align__(16) float g_dis[N_NODES];
__device__ __align__(16) int   g_cnt[N_PAD];
__device__ __align__(16) int   g_off[N_PAD + 4];
__device__ __align__(16) int   g_cursor[N_PAD];
__device__ __align__(16) int   g_bucket[N_EDGES];

// ---------------- zero counters ----------------
__global__ __launch_bounds__(256) void zero_kernel()
{
    int i = blockIdx.x * 256 + threadIdx.x;
    if (i < N_PAD) g_cnt[i] = 0;
    if (i < N_NODES) g_deg[i] = 0;
}

// ---------------- fused histogram: deg over src, cnt over dst --------------
__global__ __launch_bounds__(256) void hist_kernel(const int* __restrict__ ei)
{
    int e = blockIdx.x * 256 + threadIdx.x;
    if (e < N_EDGES) {
        atomicAdd(&g_deg[ei[e]], 1);
        atomicAdd(&g_cnt[ei[N_EDGES + e]], 1);
    }
}

// ---------------- dis = rsqrt(deg + 1 self loop) ----------------
__global__ __launch_bounds__(256) void dis_kernel()
{
    int i = blockIdx.x * 256 + threadIdx.x;
    if (i < N_NODES) {
        g_dis[i] = rsqrtf((float)(g_deg[i] + 1));
    }
}

// ---------------- tf32 helpers ----------------
__device__ __forceinline__ unsigned f2tf32(float f) {
    unsigned u;
    asm("cvt.rna.tf32.f32 %0, %1;" : "=r"(u) : "f"(f));
    return u;
}
__device__ __forceinline__ void mma_tf32(
    float& d0, float& d1, float& d2, float& d3,
    unsigned a0, unsigned a1, unsigned a2, unsigned a3,
    unsigned b0, unsigned b1)
{
    asm volatile(
        "mma.sync.aligned.m16n8k8.row.col.f32.tf32.tf32.f32 "
        "{%0,%1,%2,%3}, {%4,%5,%6,%7}, {%8,%9}, {%0,%1,%2,%3};"
        : "+f"(d0), "+f"(d1), "+f"(d2), "+f"(d3)
        : "r"(a0), "r"(a1), "r"(a2), "r"(a3), "r"(b0), "r"(b1));
}

// ---------------- GEMM via tf32 tensor cores (NO dis dependency) ------------
// g_hraw = x @ W^T + b  (fp32).  Runs concurrently with the CSR build.
#define KC 64
#define XS(r, k) smem_u[(r) * 68 + (k)]
#define WS(n, k) smem_u[128 * 68 + (n) * 68 + (k)]

__global__ __launch_bounds__(256, 2) void gemm_mma_kernel(
    const float* __restrict__ x, const float* __restrict__ W,
    const float* __restrict__ b)
{
    extern __shared__ unsigned smem_u[];   // 2 * 128 * 68 * 4 = 69632 B

    const int tid  = threadIdx.x;
    const int lane = tid & 31;
    const int warp = tid >> 5;            // 0..7
    const int r    = lane >> 2;           // groupID 0..7
    const int c    = lane & 3;            // threadID-in-group 0..3
    const int lrow = warp * 16;
    const int m0   = blockIdx.x * 128;

    float acc[16][4];
#pragma unroll
    for (int t = 0; t < 16; t++)
#pragma unroll
        for (int j = 0; j < 4; j++) acc[t][j] = 0.f;

#pragma unroll
    for (int chunk = 0; chunk < 2; chunk++) {
        const int kc = chunk * KC;
#pragma unroll
        for (int i = 0; i < 8; i++) {
            int f = tid + i * 256;         // 0..2047
            int row = f >> 4;
            int kq  = f & 15;
            int grow = m0 + row;
            if (grow >= N_NODES) grow = N_NODES - 1;
            float4 xv = *reinterpret_cast<const float4*>(&x[(size_t)grow * D + kc + kq * 4]);
            uint4 xu = make_uint4(f2tf32(xv.x), f2tf32(xv.y), f2tf32(xv.z), f2tf32(xv.w));
            *reinterpret_cast<uint4*>(&XS(row, kq * 4)) = xu;
            float4 wv = *reinterpret_cast<const float4*>(&W[(size_t)row * D + kc + kq * 4]);
            uint4 wu = make_uint4(f2tf32(wv.x), f2tf32(wv.y), f2tf32(wv.z), f2tf32(wv.w));
            *reinterpret_cast<uint4*>(&WS(row, kq * 4)) = wu;
        }
        __syncthreads();

#pragma unroll
        for (int s = 0; s < 8; s++) {
            unsigned a0 = XS(lrow + r,     s * 8 + c);
            unsigned a1 = XS(lrow + r + 8, s * 8 + c);
            unsigned a2 = XS(lrow + r,     s * 8 + c + 4);
            unsigned a3 = XS(lrow + r + 8, s * 8 + c + 4);
#pragma unroll
            for (int t = 0; t < 16; t++) {
                unsigned b0 = WS(t * 8 + r, s * 8 + c);
                unsigned b1 = WS(t * 8 + r, s * 8 + c + 4);
                mma_tf32(acc[t][0], acc[t][1], acc[t][2], acc[t][3],
                         a0, a1, a2, a3, b0, b1);
            }
        }
        __syncthreads();
    }

    const int row_a = m0 + lrow + r;
    const int row_b = row_a + 8;
#pragma unroll
    for (int t = 0; t < 16; t++) {
        int col0 = t * 8 + c * 2;
        float2 bias = *reinterpret_cast<const float2*>(&b[col0]);
        if (row_a < N_NODES) {
            *reinterpret_cast<float2*>(&g_hraw[(size_t)row_a * D + col0]) =
                make_float2(acc[t][0] + bias.x, acc[t][1] + bias.y);
        }
        if (row_b < N_NODES) {
            *reinterpret_cast<float2*>(&g_hraw[(size_t)row_b * D + col0]) =
                make_float2(acc[t][2] + bias.x, acc[t][3] + bias.y);
        }
    }
}

// ---------------- scale: h' = fp16( dis[row] * h_raw[row] ) -----------------
__global__ __launch_bounds__(256) void scale_kernel()
{
    int gid = blockIdx.x * 256 + threadIdx.x;   // N_NODES*16 threads
    int row = gid >> 4, q = gid & 15;
    if (row >= N_NODES) return;
    float dd = g_dis[row];
    const float4* src = reinterpret_cast<const float4*>(&g_hraw[(size_t)row * D + q * 8]);
    float4 f0 = src[0], f1 = src[1];
    __half2 h0 = __floats2half2_rn(dd * f0.x, dd * f0.y);
    __half2 h1 = __floats2half2_rn(dd * f0.z, dd * f0.w);
    __half2 h2 = __floats2half2_rn(dd * f1.x, dd * f1.y);
    __half2 h3 = __floats2half2_rn(dd * f1.z, dd * f1.w);
    uint4 u;
    u.x = *reinterpret_cast<unsigned*>(&h0);
    u.y = *reinterpret_cast<unsigned*>(&h1);
    u.z = *reinterpret_cast<unsigned*>(&h2);
    u.w = *reinterpret_cast<unsigned*>(&h3);
    reinterpret_cast<uint4*>(g_h)[(size_t)row * 16 + q] = u;
}

// ---------------- single-block exclusive scan over g_cnt -------------------
__global__ __launch_bounds__(1024) void scan_kernel()
{
    __shared__ int ssum[1024];
    const int tid = threadIdx.x;
    const int4* cnt4 = reinterpret_cast<const int4*>(g_cnt);

    int s = 0;
#pragma unroll
    for (int k = 0; k < 25; k++) {
        int4 v = cnt4[tid * 25 + k];
        s += v.x + v.y + v.z + v.w;
    }
    ssum[tid] = s;
    __syncthreads();

    for (int d = 1; d < 1024; d <<= 1) {
        int v = (tid >= d) ? ssum[tid - d] : 0;
        __syncthreads();
        ssum[tid] += v;
        __syncthreads();
    }
    int running = (tid == 0) ? 0 : ssum[tid - 1];

    int4* off4 = reinterpret_cast<int4*>(g_off);
    int4* cur4 = reinterpret_cast<int4*>(g_cursor);
#pragma unroll
    for (int k = 0; k < 25; k++) {
        int4 cc = cnt4[tid * 25 + k];
        int4 o;
        o.x = running;              running += cc.x;
        o.y = running;              running += cc.y;
        o.z = running;              running += cc.z;
        o.w = running;              running += cc.w;
        off4[tid * 25 + k] = o;
        cur4[tid * 25 + k] = o;
    }
}

// ---------------- bucket fill: group src ids by dst -------------------------
__global__ __launch_bounds__(256) void fill_kernel(const int* __restrict__ ei)
{
    int e = blockIdx.x * 256 + threadIdx.x;
    if (e < N_EDGES) {
        int src = ei[e];
        int dst = ei[N_EDGES + e];
        int pos = atomicAdd(&g_cursor[dst], 1);
        g_bucket[pos] = src;
    }
}

// ---------------- gather: warp per node (R8 version, 181us baseline) --------
#define ACC4(U) do {                                                          \
    float2 f_;                                                                \
    f_ = __half22float2(*reinterpret_cast<__half2*>(&(U).x)); a0.x += f_.x; a0.y += f_.y; \
    f_ = __half22float2(*reinterpret_cast<__half2*>(&(U).y)); a1.x += f_.x; a1.y += f_.y; \
    f_ = __half22float2(*reinterpret_cast<__half2*>(&(U).z)); a2.x += f_.x; a2.y += f_.y; \
    f_ = __half22float2(*reinterpret_cast<__half2*>(&(U).w)); a3.x += f_.x; a3.y += f_.y; \
} while (0)

__global__ __launch_bounds__(256) void gather_kernel(float* __restrict__ out)
{
    const int node = blockIdx.x * 8 + (threadIdx.x >> 5);
    if (node >= N_NODES) return;
    const int lane = threadIdx.x & 31;
    const int hf   = lane >> 4;      // 0/1 half-warp
    const int sub  = lane & 15;      // 16 lanes cover a 256B fp16 row
    const unsigned FULL = 0xffffffffu;

    const int start = g_off[node];
    const int end   = g_off[node + 1];
    const int cnt   = end - start;
    const float dd  = g_dis[node];
    const uint4* hbase = reinterpret_cast<const uint4*>(g_h);

    int idx = (lane < cnt) ? g_bucket[start + lane] : 0;

    float2 a0 = make_float2(0.f, 0.f), a1 = a0, a2 = a0, a3 = a0;

    if (hf == 0) {
        uint4 u = hbase[(size_t)node * 16 + sub];
        a0 = __half22float2(*reinterpret_cast<__half2*>(&u.x));
        a1 = __half22float2(*reinterpret_cast<__half2*>(&u.y));
        a2 = __half22float2(*reinterpret_cast<__half2*>(&u.z));
        a3 = __half22float2(*reinterpret_cast<__half2*>(&u.w));
    }

    const int m = cnt < 32 ? cnt : 32;
    const int full8 = m & ~7;        // warp-uniform

    for (int base = 0; base < full8; base += 8) {
        int s0 = __shfl_sync(FULL, idx, base + hf);
        int s1 = __shfl_sync(FULL, idx, base + hf + 2);
        int s2 = __shfl_sync(FULL, idx, base + hf + 4);
        int s3 = __shfl_sync(FULL, idx, base + hf + 6);
        uint4 u0 = hbase[(size_t)s0 * 16 + sub];
        uint4 u1 = hbase[(size_t)s1 * 16 + sub];
        uint4 u2 = hbase[(size_t)s2 * 16 + sub];
        uint4 u3 = hbase[(size_t)s3 * 16 + sub];
        ACC4(u0); ACC4(u1); ACC4(u2); ACC4(u3);
    }
    for (int rr = full8; rr < m; rr += 2) {
        int ee = rr + hf;
        int s0 = __shfl_sync(FULL, idx, ee & 31);
        if (ee < m) {
            uint4 u0 = hbase[(size_t)s0 * 16 + sub];
            ACC4(u0);
        }
    }
    for (int j = start + 32 + hf; j < end; j += 2) {
        int s0 = g_bucket[j];
        uint4 u0 = hbase[(size_t)s0 * 16 + sub];
        ACC4(u0);
    }

    a0.x += __shfl_xor_sync(FULL, a0.x, 16);
    a0.y += __shfl_xor_sync(FULL, a0.y, 16);
    a1.x += __shfl_xor_sync(FULL, a1.x, 16);
    a1.y += __shfl_xor_sync(FULL, a1.y, 16);
    a2.x += __shfl_xor_sync(FULL, a2.x, 16);
    a2.y += __shfl_xor_sync(FULL, a2.y, 16);
    a3.x += __shfl_xor_sync(FULL, a3.x, 16);
    a3.y += __shfl_xor_sync(FULL, a3.y, 16);

    const float coef = 0.125f;  // sqrt(2/128)
    float4 v;
    if (hf == 0) {
        v.x = a0.x; v.y = a0.y; v.z = a1.x; v.w = a1.y;
    } else {
        v.x = a2.x; v.y = a2.y; v.z = a3.x; v.w = a3.y;
    }
    v.x = coef * fmaxf(dd * v.x, 0.f);
    v.y = coef * fmaxf(dd * v.y, 0.f);
    v.z = coef * fmaxf(dd * v.z, 0.f);
    v.w = coef * fmaxf(dd * v.w, 0.f);
    *reinterpret_cast<float4*>(&out[(size_t)node * D + sub * 8 + hf * 4]) = v;
}

// ---------------- resources created before any harness checkpoint ----------
struct KLResources {
    cudaStream_t s2;
    cudaEvent_t ev_fork, ev_join;
    KLResources() {
        cudaStreamCreateWithFlags(&s2, cudaStreamNonBlocking);
        cudaEventCreateWithFlags(&ev_fork, cudaEventDisableTiming);
        cudaEventCreateWithFlags(&ev_join, cudaEventDisableTiming);
        cudaFuncSetAttribute(gemm_mma_kernel,
                             cudaFuncAttributeMaxDynamicSharedMemorySize,
                             2 * 128 * 68 * 4);
    }
};
static KLResources g_res;

extern "C" void kernel_launch(void* const* d_in, const int* in_sizes, int n_in,
                              void* d_out, int out_size)
{
    const float* x  = (const float*)d_in[0];
    const int*   ei = (const int*)d_in[1];   // int32: JAX x64 disabled
    const float* W  = (const float*)d_in[2];
    const float* b  = (const float*)d_in[3];
    float* out = (float*)d_out;

    const int GEMM_SMEM = 2 * 128 * 68 * 4;  // 69632 B

    // fork: GEMM (no dependencies) runs on s2 concurrently with CSR build
    cudaEventRecord(g_res.ev_fork, 0);
    cudaStreamWaitEvent(g_res.s2, g_res.ev_fork, 0);
    gemm_mma_kernel<<<(N_NODES + 127) / 128, 256, GEMM_SMEM, g_res.s2>>>(x, W, b);
    cudaEventRecord(g_res.ev_join, g_res.s2);

    // CSR build chain on the origin stream
    zero_kernel<<<(N_PAD + 255) / 256, 256>>>();
    hist_kernel<<<(N_EDGES + 255) / 256, 256>>>(ei);
    scan_kernel<<<1, 1024>>>();
    dis_kernel<<<(N_NODES + 255) / 256, 256>>>();
    fill_kernel<<<(N_EDGES + 255) / 256, 256>>>(ei);

    // join: scale needs GEMM output + dis
    cudaStreamWaitEvent(0, g_res.ev_join, 0);
    scale_kernel<<<(N_NODES * 16) / 256, 256>>>();
    gather_kernel<<<(N_NODES + 7) / 8, 256>>>(out);
}

// round 12
// speedup vs baseline: 1.1785x; 1.0659x over previous
#include <cuda_runtime.h>
#include <cuda_fp16.h>
#include <cstdint>

#define N_NODES 100000
#define N_EDGES 1600000
#define D 128
#define N_PAD 102400   // 100 blocks * 1024 ints, zero-padded tail

// Scratch (no cudaMalloc allowed)
__device__ __align__(16) float   g_hraw[(size_t)N_NODES * D];     // xW^T+b, fp32
__device__ __align__(16) __half2 g_h[(size_t)N_NODES * (D / 2)];  // dis-premult, fp16
__device__ __align__(16) int   g_deg[N_NODES];
__device__ __align__(16) float g_dis[N_NODES];
__device__ __align__(16) int   g_cnt[N_PAD];
__device__ __align__(16) int   g_off[N_PAD + 4];
__device__ __align__(16) int   g_cursor[N_PAD];
__device__ __align__(16) int   g_bucket[N_EDGES];
__device__ __align__(16) int   g_bsum[128];    // per-block totals (100 used)
__device__ __align__(16) int   g_bbase[128];   // exclusive prefix of block totals

// ---------------- zero counters ----------------
__global__ __launch_bounds__(256) void zero_kernel()
{
    int i = blockIdx.x * 256 + threadIdx.x;
    if (i < N_PAD) g_cnt[i] = 0;
    if (i < N_NODES) g_deg[i] = 0;
}

// ---------------- fused histogram: deg over src, cnt over dst --------------
__global__ __launch_bounds__(256) void hist_kernel(const int* __restrict__ ei)
{
    int e = blockIdx.x * 256 + threadIdx.x;
    if (e < N_EDGES) {
        atomicAdd(&g_deg[ei[e]], 1);
        atomicAdd(&g_cnt[ei[N_EDGES + e]], 1);
    }
}

// ---------------- dis = rsqrt(deg + 1 self loop) ----------------
__global__ __launch_bounds__(256) void dis_kernel()
{
    int i = blockIdx.x * 256 + threadIdx.x;
    if (i < N_NODES) {
        g_dis[i] = rsqrtf((float)(g_deg[i] + 1));
    }
}

// ---------------- 3-phase exclusive scan over g_cnt ------------------------
// Phase 1: 100 blocks x 256 thr; each block sums 1024 ints -> g_bsum[blk]
__global__ __launch_bounds__(256) void scan_p1()
{
    __shared__ int wsum[8];
    const int tid = threadIdx.x;
    int4 v = reinterpret_cast<const int4*>(g_cnt)[blockIdx.x * 256 + tid];
    int s = v.x + v.y + v.z + v.w;
#pragma unroll
    for (int o = 16; o > 0; o >>= 1)
        s += __shfl_down_sync(0xffffffffu, s, o);
    if ((tid & 31) == 0) wsum[tid >> 5] = s;
    __syncthreads();
    if (tid < 8) {
        int t = wsum[tid];
#pragma unroll
        for (int o = 4; o > 0; o >>= 1)
            t += __shfl_down_sync(0xffu, t, o);
        if (tid == 0) g_bsum[blockIdx.x] = t;
    }
}

// Phase 2: 1 block x 128 thr; exclusive scan of 100 block sums
__global__ __launch_bounds__(128) void scan_p2()
{
    __shared__ int sh[128];
    const int tid = threadIdx.x;
    sh[tid] = (tid < 100) ? g_bsum[tid] : 0;
    __syncthreads();
    for (int d = 1; d < 128; d <<= 1) {
        int v = (tid >= d) ? sh[tid - d] : 0;
        __syncthreads();
        sh[tid] += v;
        __syncthreads();
    }
    g_bbase[tid] = (tid == 0) ? 0 : sh[tid - 1];   // exclusive
}

// Phase 3: 100 blocks; local exclusive scan + block base -> g_off, g_cursor
__global__ __launch_bounds__(256) void scan_p3()
{
    __shared__ int wbase[8];
    const int tid  = threadIdx.x;
    const int lane = tid & 31;
    const int wid  = tid >> 5;
    const int gi   = blockIdx.x * 256 + tid;

    int4 v = reinterpret_cast<const int4*>(g_cnt)[gi];
    int tot = v.x + v.y + v.z + v.w;

    // warp inclusive scan of per-thread totals
    int incl = tot;
#pragma unroll
    for (int o = 1; o < 32; o <<= 1) {
        int t = __shfl_up_sync(0xffffffffu, incl, o);
        if (lane >= o) incl += t;
    }
    if (lane == 31) wbase[wid] = incl;
    __syncthreads();
    if (tid < 8) {
        int t = wbase[tid];
        // exclusive scan of 8 warp totals (serial in warp 0 lanes)
        int e = 0;
        for (int k = 0; k < 8; k++) {
            int vk = __shfl_sync(0xffu, t, k);
            if (tid == k) { int tmp = e; e = tmp; }
            if (tid > k) e += vk;
        }
        wbase[tid] = e;
    }
    __syncthreads();

    int base = g_bbase[blockIdx.x] + wbase[wid] + (incl - tot);
    int4 o;
    o.x = base;
    o.y = base + v.x;
    o.z = base + v.x + v.y;
    o.w = base + v.x + v.y + v.z;
    reinterpret_cast<int4*>(g_off)[gi]    = o;
    reinterpret_cast<int4*>(g_cursor)[gi] = o;
}

// ---------------- tf32 helpers ----------------
__device__ __forceinline__ unsigned f2tf32(float f) {
    unsigned u;
    asm("cvt.rna.tf32.f32 %0, %1;" : "=r"(u) : "f"(f));
    return u;
}
__device__ __forceinline__ void mma_tf32(
    float& d0, float& d1, float& d2, float& d3,
    unsigned a0, unsigned a1, unsigned a2, unsigned a3,
    unsigned b0, unsigned b1)
{
    asm volatile(
        "mma.sync.aligned.m16n8k8.row.col.f32.tf32.tf32.f32 "
        "{%0,%1,%2,%3}, {%4,%5,%6,%7}, {%8,%9}, {%0,%1,%2,%3};"
        : "+f"(d0), "+f"(d1), "+f"(d2), "+f"(d3)
        : "r"(a0), "r"(a1), "r"(a2), "r"(a3), "r"(b0), "r"(b1));
}

// ---------------- GEMM via tf32 tensor cores (NO dis dependency) ------------
#define KC 64
#define XS(r, k) smem_u[(r) * 68 + (k)]
#define WS(n, k) smem_u[128 * 68 + (n) * 68 + (k)]

__global__ __launch_bounds__(256, 2) void gemm_mma_kernel(
    const float* __restrict__ x, const float* __restrict__ W,
    const float* __restrict__ b)
{
    extern __shared__ unsigned smem_u[];   // 69632 B

    const int tid  = threadIdx.x;
    const int lane = tid & 31;
    const int warp = tid >> 5;
    const int r    = lane >> 2;
    const int c    = lane & 3;
    const int lrow = warp * 16;
    const int m0   = blockIdx.x * 128;

    float acc[16][4];
#pragma unroll
    for (int t = 0; t < 16; t++)
#pragma unroll
        for (int j = 0; j < 4; j++) acc[t][j] = 0.f;

#pragma unroll
    for (int chunk = 0; chunk < 2; chunk++) {
        const int kc = chunk * KC;
#pragma unroll
        for (int i = 0; i < 8; i++) {
            int f = tid + i * 256;
            int row = f >> 4;
            int kq  = f & 15;
            int grow = m0 + row;
            if (grow >= N_NODES) grow = N_NODES - 1;
            float4 xv = *reinterpret_cast<const float4*>(&x[(size_t)grow * D + kc + kq * 4]);
            uint4 xu = make_uint4(f2tf32(xv.x), f2tf32(xv.y), f2tf32(xv.z), f2tf32(xv.w));
            *reinterpret_cast<uint4*>(&XS(row, kq * 4)) = xu;
            float4 wv = *reinterpret_cast<const float4*>(&W[(size_t)row * D + kc + kq * 4]);
            uint4 wu = make_uint4(f2tf32(wv.x), f2tf32(wv.y), f2tf32(wv.z), f2tf32(wv.w));
            *reinterpret_cast<uint4*>(&WS(row, kq * 4)) = wu;
        }
        __syncthreads();

#pragma unroll
        for (int s = 0; s < 8; s++) {
            unsigned a0 = XS(lrow + r,     s * 8 + c);
            unsigned a1 = XS(lrow + r + 8, s * 8 + c);
            unsigned a2 = XS(lrow + r,     s * 8 + c + 4);
            unsigned a3 = XS(lrow + r + 8, s * 8 + c + 4);
#pragma unroll
            for (int t = 0; t < 16; t++) {
                unsigned b0 = WS(t * 8 + r, s * 8 + c);
                unsigned b1 = WS(t * 8 + r, s * 8 + c + 4);
                mma_tf32(acc[t][0], acc[t][1], acc[t][2], acc[t][3],
                         a0, a1, a2, a3, b0, b1);
            }
        }
        __syncthreads();
    }

    const int row_a = m0 + lrow + r;
    const int row_b = row_a + 8;
#pragma unroll
    for (int t = 0; t < 16; t++) {
        int col0 = t * 8 + c * 2;
        float2 bias = *reinterpret_cast<const float2*>(&b[col0]);
        if (row_a < N_NODES) {
            *reinterpret_cast<float2*>(&g_hraw[(size_t)row_a * D + col0]) =
                make_float2(acc[t][0] + bias.x, acc[t][1] + bias.y);
        }
        if (row_b < N_NODES) {
            *reinterpret_cast<float2*>(&g_hraw[(size_t)row_b * D + col0]) =
                make_float2(acc[t][2] + bias.x, acc[t][3] + bias.y);
        }
    }
}

// ---------------- scale: h' = fp16( dis[row] * h_raw[row] ) -----------------
__global__ __launch_bounds__(256) void scale_kernel()
{
    int gid = blockIdx.x * 256 + threadIdx.x;   // N_NODES*16 threads
    int row = gid >> 4, q = gid & 15;
    if (row >= N_NODES) return;
    float dd = g_dis[row];
    const float4* src = reinterpret_cast<const float4*>(&g_hraw[(size_t)row * D + q * 8]);
    float4 f0 = src[0], f1 = src[1];
    __half2 h0 = __floats2half2_rn(dd * f0.x, dd * f0.y);
    __half2 h1 = __floats2half2_rn(dd * f0.z, dd * f0.w);
    __half2 h2 = __floats2half2_rn(dd * f1.x, dd * f1.y);
    __half2 h3 = __floats2half2_rn(dd * f1.z, dd * f1.w);
    uint4 u;
    u.x = *reinterpret_cast<unsigned*>(&h0);
    u.y = *reinterpret_cast<unsigned*>(&h1);
    u.z = *reinterpret_cast<unsigned*>(&h2);
    u.w = *reinterpret_cast<unsigned*>(&h3);
    reinterpret_cast<uint4*>(g_h)[(size_t)row * 16 + q] = u;
}

// ---------------- bucket fill: group src ids by dst -------------------------
__global__ __launch_bounds__(256) void fill_kernel(const int* __restrict__ ei)
{
    int e = blockIdx.x * 256 + threadIdx.x;
    if (e < N_EDGES) {
        int src = ei[e];
        int dst = ei[N_EDGES + e];
        int pos = atomicAdd(&g_cursor[dst], 1);
        g_bucket[pos] = src;
    }
}

// ---------------- gather: warp per node (R8 version) -------------------------
#define ACC4(U) do {                                                          \
    float2 f_;                                                                \
    f_ = __half22float2(*reinterpret_cast<__half2*>(&(U).x)); a0.x += f_.x; a0.y += f_.y; \
    f_ = __half22float2(*reinterpret_cast<__half2*>(&(U).y)); a1.x += f_.x; a1.y += f_.y; \
    f_ = __half22float2(*reinterpret_cast<__half2*>(&(U).z)); a2.x += f_.x; a2.y += f_.y; \
    f_ = __half22float2(*reinterpret_cast<__half2*>(&(U).w)); a3.x += f_.x; a3.y += f_.y; \
} while (0)

__global__ __launch_bounds__(256) void gather_kernel(float* __restrict__ out)
{
    const int node = blockIdx.x * 8 + (threadIdx.x >> 5);
    if (node >= N_NODES) return;
    const int lane = threadIdx.x & 31;
    const int hf   = lane >> 4;
    const int sub  = lane & 15;
    const unsigned FULL = 0xffffffffu;

    const int start = g_off[node];
    const int end   = g_off[node + 1];
    const int cnt   = end - start;
    const float dd  = g_dis[node];
    const uint4* hbase = reinterpret_cast<const uint4*>(g_h);

    int idx = (lane < cnt) ? g_bucket[start + lane] : 0;

    float2 a0 = make_float2(0.f, 0.f), a1 = a0, a2 = a0, a3 = a0;

    if (hf == 0) {
        uint4 u = hbase[(size_t)node * 16 + sub];
        a0 = __half22float2(*reinterpret_cast<__half2*>(&u.x));
        a1 = __half22float2(*reinterpret_cast<__half2*>(&u.y));
        a2 = __half22float2(*reinterpret_cast<__half2*>(&u.z));
        a3 = __half22float2(*reinterpret_cast<__half2*>(&u.w));
    }

    const int m = cnt < 32 ? cnt : 32;
    const int full8 = m & ~7;

    for (int base = 0; base < full8; base += 8) {
        int s0 = __shfl_sync(FULL, idx, base + hf);
        int s1 = __shfl_sync(FULL, idx, base + hf + 2);
        int s2 = __shfl_sync(FULL, idx, base + hf + 4);
        int s3 = __shfl_sync(FULL, idx, base + hf + 6);
        uint4 u0 = hbase[(size_t)s0 * 16 + sub];
        uint4 u1 = hbase[(size_t)s1 * 16 + sub];
        uint4 u2 = hbase[(size_t)s2 * 16 + sub];
        uint4 u3 = hbase[(size_t)s3 * 16 + sub];
        ACC4(u0); ACC4(u1); ACC4(u2); ACC4(u3);
    }
    for (int rr = full8; rr < m; rr += 2) {
        int ee = rr + hf;
        int s0 = __shfl_sync(FULL, idx, ee & 31);
        if (ee < m) {
            uint4 u0 = hbase[(size_t)s0 * 16 + sub];
            ACC4(u0);
        }
    }
    for (int j = start + 32 + hf; j < end; j += 2) {
        int s0 = g_bucket[j];
        uint4 u0 = hbase[(size_t)s0 * 16 + sub];
        ACC4(u0);
    }

    a0.x += __shfl_xor_sync(FULL, a0.x, 16);
    a0.y += __shfl_xor_sync(FULL, a0.y, 16);
    a1.x += __shfl_xor_sync(FULL, a1.x, 16);
    a1.y += __shfl_xor_sync(FULL, a1.y, 16);
    a2.x += __shfl_xor_sync(FULL, a2.x, 16);
    a2.y += __shfl_xor_sync(FULL, a2.y, 16);
    a3.x += __shfl_xor_sync(FULL, a3.x, 16);
    a3.y += __shfl_xor_sync(FULL, a3.y, 16);

    const float coef = 0.125f;  // sqrt(2/128)
    float4 v;
    if (hf == 0) {
        v.x = a0.x; v.y = a0.y; v.z = a1.x; v.w = a1.y;
    } else {
        v.x = a2.x; v.y = a2.y; v.z = a3.x; v.w = a3.y;
    }
    v.x = coef * fmaxf(dd * v.x, 0.f);
    v.y = coef * fmaxf(dd * v.y, 0.f);
    v.z = coef * fmaxf(dd * v.z, 0.f);
    v.w = coef * fmaxf(dd * v.w, 0.f);
    *reinterpret_cast<float4*>(&out[(size_t)node * D + sub * 8 + hf * 4]) = v;
}

// ---------------- resources created before any harness checkpoint ----------
struct KLResources {
    cudaStream_t s2;
    cudaEvent_t ev_fork, ev_dis, ev_join;
    KLResources() {
        cudaStreamCreateWithFlags(&s2, cudaStreamNonBlocking);
        cudaEventCreateWithFlags(&ev_fork, cudaEventDisableTiming);
        cudaEventCreateWithFlags(&ev_dis, cudaEventDisableTiming);
        cudaEventCreateWithFlags(&ev_join, cudaEventDisableTiming);
        cudaFuncSetAttribute(gemm_mma_kernel,
                             cudaFuncAttributeMaxDynamicSharedMemorySize,
                             2 * 128 * 68 * 4);
    }
};
static KLResources g_res;

extern "C" void kernel_launch(void* const* d_in, const int* in_sizes, int n_in,
                              void* d_out, int out_size)
{
    const float* x  = (const float*)d_in[0];
    const int*   ei = (const int*)d_in[1];   // int32: JAX x64 disabled
    const float* W  = (const float*)d_in[2];
    const float* b  = (const float*)d_in[3];
    float* out = (float*)d_out;

    const int GEMM_SMEM = 2 * 128 * 68 * 4;  // 69632 B

    // fork: GEMM (no dependencies) on s2, concurrent with CSR build
    cudaEventRecord(g_res.ev_fork, 0);
    cudaStreamWaitEvent(g_res.s2, g_res.ev_fork, 0);
    gemm_mma_kernel<<<(N_NODES + 127) / 128, 256, GEMM_SMEM, g_res.s2>>>(x, W, b);

    // CSR build chain on origin stream
    zero_kernel<<<(N_PAD + 255) / 256, 256>>>();
    hist_kernel<<<(N_EDGES + 255) / 256, 256>>>(ei);
    dis_kernel<<<(N_NODES + 255) / 256, 256>>>();
    cudaEventRecord(g_res.ev_dis, 0);
    scan_p1<<<100, 256>>>();
    scan_p2<<<1, 128>>>();
    scan_p3<<<100, 256>>>();
    fill_kernel<<<(N_EDGES + 255) / 256, 256>>>(ei);

    // scale on s2 after GEMM + dis (overlaps with scan/fill on origin stream)
    cudaStreamWaitEvent(g_res.s2, g_res.ev_dis, 0);
    scale_kernel<<<(N_NODES * 16) / 256, 256, 0, g_res.s2>>>();
    cudaEventRecord(g_res.ev_join, g_res.s2);

    // join: gather needs CSR (origin) + h' (s2)
    cudaStreamWaitEvent(0, g_res.ev_join, 0);
    gather_kernel<<<(N_NODES + 7) / 8, 256>>>(out);
}

// round 13
// speedup vs baseline: 1.6388x; 1.3905x over previous
#include <cuda_runtime.h>
#include <cuda_fp16.h>
#include <cstdint>

#define N_NODES 100000
#define N_EDGES 1600000
#define D 128
#define N_PAD 102400   // 100 blocks * 1024 ints, zero-padded tail

// Scratch (no cudaMalloc allowed). g_cnt/g_deg are zero at entry of every
// call: BSS init covers call 1, the trailing zero_kernel covers the rest.
__device__ __align__(16) float   g_hraw[(size_t)N_NODES * D];     // xW^T+b, fp32
__device__ __align__(16) __half2 g_h[(size_t)N_NODES * (D / 2)];  // dis-premult, fp16
__device__ __align__(16) int   g_deg[N_NODES];
__device__ __align__(16) float g_dis[N_NODES];
__device__ __align__(16) int   g_cnt[N_PAD];
__device__ __align__(16) int   g_off[N_PAD + 4];
__device__ __align__(16) int   g_cursor[N_PAD];
__device__ __align__(16) int   g_bucket[N_EDGES];
__device__ __align__(16) int   g_bsum[128];
__device__ __align__(16) int   g_bbase[128];

// ---------------- zero counters (runs at END of call, for the next one) ----
__global__ __launch_bounds__(256) void zero_kernel()
{
    int i = blockIdx.x * 256 + threadIdx.x;
    if (i < N_PAD) g_cnt[i] = 0;
    if (i < N_NODES) g_deg[i] = 0;
}

// ---------------- fused histogram: deg over src, cnt over dst --------------
__global__ __launch_bounds__(256) void hist_kernel(const int* __restrict__ ei)
{
    int e = blockIdx.x * 256 + threadIdx.x;
    if (e < N_EDGES) {
        atomicAdd(&g_deg[ei[e]], 1);
        atomicAdd(&g_cnt[ei[N_EDGES + e]], 1);
    }
}

// ---------------- dis = rsqrt(deg + 1 self loop) ----------------
__global__ __launch_bounds__(256) void dis_kernel()
{
    int i = blockIdx.x * 256 + threadIdx.x;
    if (i < N_NODES) {
        g_dis[i] = rsqrtf((float)(g_deg[i] + 1));
    }
}

// ---------------- 3-phase exclusive scan over g_cnt ------------------------
__global__ __launch_bounds__(256) void scan_p1()
{
    __shared__ int wsum[8];
    const int tid = threadIdx.x;
    int4 v = reinterpret_cast<const int4*>(g_cnt)[blockIdx.x * 256 + tid];
    int s = v.x + v.y + v.z + v.w;
#pragma unroll
    for (int o = 16; o > 0; o >>= 1)
        s += __shfl_down_sync(0xffffffffu, s, o);
    if ((tid & 31) == 0) wsum[tid >> 5] = s;
    __syncthreads();
    if (tid < 8) {
        int t = wsum[tid];
#pragma unroll
        for (int o = 4; o > 0; o >>= 1)
            t += __shfl_down_sync(0xffu, t, o);
        if (tid == 0) g_bsum[blockIdx.x] = t;
    }
}

__global__ __launch_bounds__(128) void scan_p2()
{
    __shared__ int sh[128];
    const int tid = threadIdx.x;
    sh[tid] = (tid < 100) ? g_bsum[tid] : 0;
    __syncthreads();
    for (int d = 1; d < 128; d <<= 1) {
        int v = (tid >= d) ? sh[tid - d] : 0;
        __syncthreads();
        sh[tid] += v;
        __syncthreads();
    }
    g_bbase[tid] = (tid == 0) ? 0 : sh[tid - 1];
}

__global__ __launch_bounds__(256) void scan_p3()
{
    __shared__ int wbase[8];
    const int tid  = threadIdx.x;
    const int lane = tid & 31;
    const int wid  = tid >> 5;
    const int gi   = blockIdx.x * 256 + tid;

    int4 v = reinterpret_cast<const int4*>(g_cnt)[gi];
    int tot = v.x + v.y + v.z + v.w;

    int incl = tot;
#pragma unroll
    for (int o = 1; o < 32; o <<= 1) {
        int t = __shfl_up_sync(0xffffffffu, incl, o);
        if (lane >= o) incl += t;
    }
    if (lane == 31) wbase[wid] = incl;
    __syncthreads();
    if (tid < 8) {
        int t = wbase[tid];
        int e = 0;
        for (int k = 0; k < 8; k++) {
            int vk = __shfl_sync(0xffu, t, k);
            if (tid > k) e += vk;
        }
        wbase[tid] = e;
    }
    __syncthreads();

    int base = g_bbase[blockIdx.x] + wbase[wid] + (incl - tot);
    int4 o;
    o.x = base;
    o.y = base + v.x;
    o.z = base + v.x + v.y;
    o.w = base + v.x + v.y + v.z;
    reinterpret_cast<int4*>(g_off)[gi]    = o;
    reinterpret_cast<int4*>(g_cursor)[gi] = o;
}

// ---------------- tf32 helpers ----------------
__device__ __forceinline__ unsigned f2tf32(float f) {
    unsigned u;
    asm("cvt.rna.tf32.f32 %0, %1;" : "=r"(u) : "f"(f));
    return u;
}
__device__ __forceinline__ void mma_tf32(
    float& d0, float& d1, float& d2, float& d3,
    unsigned a0, unsigned a1, unsigned a2, unsigned a3,
    unsigned b0, unsigned b1)
{
    asm volatile(
        "mma.sync.aligned.m16n8k8.row.col.f32.tf32.tf32.f32 "
        "{%0,%1,%2,%3}, {%4,%5,%6,%7}, {%8,%9}, {%0,%1,%2,%3};"
        : "+f"(d0), "+f"(d1), "+f"(d2), "+f"(d3)
        : "r"(a0), "r"(a1), "r"(a2), "r"(a3), "r"(b0), "r"(b1));
}

// ---------------- GEMM via tf32 tensor cores (NO dis dependency) ------------
#define KC 64
#define XS(r, k) smem_u[(r) * 68 + (k)]
#define WS(n, k) smem_u[128 * 68 + (n) * 68 + (k)]

__global__ __launch_bounds__(256, 2) void gemm_mma_kernel(
    const float* __restrict__ x, const float* __restrict__ W,
    const float* __restrict__ b)
{
    extern __shared__ unsigned smem_u[];   // 69632 B

    const int tid  = threadIdx.x;
    const int lane = tid & 31;
    const int warp = tid >> 5;
    const int r    = lane >> 2;
    const int c    = lane & 3;
    const int lrow = warp * 16;
    const int m0   = blockIdx.x * 128;

    float acc[16][4];
#pragma unroll
    for (int t = 0; t < 16; t++)
#pragma unroll
        for (int j = 0; j < 4; j++) acc[t][j] = 0.f;

#pragma unroll
    for (int chunk = 0; chunk < 2; chunk++) {
        const int kc = chunk * KC;
#pragma unroll
        for (int i = 0; i < 8; i++) {
            int f = tid + i * 256;
            int row = f >> 4;
            int kq  = f & 15;
            int grow = m0 + row;
            if (grow >= N_NODES) grow = N_NODES - 1;
            float4 xv = *reinterpret_cast<const float4*>(&x[(size_t)grow * D + kc + kq * 4]);
            uint4 xu = make_uint4(f2tf32(xv.x), f2tf32(xv.y), f2tf32(xv.z), f2tf32(xv.w));
            *reinterpret_cast<uint4*>(&XS(row, kq * 4)) = xu;
            float4 wv = *reinterpret_cast<const float4*>(&W[(size_t)row * D + kc + kq * 4]);
            uint4 wu = make_uint4(f2tf32(wv.x), f2tf32(wv.y), f2tf32(wv.z), f2tf32(wv.w));
            *reinterpret_cast<uint4*>(&WS(row, kq * 4)) = wu;
        }
        __syncthreads();

#pragma unroll
        for (int s = 0; s < 8; s++) {
            unsigned a0 = XS(lrow + r,     s * 8 + c);
            unsigned a1 = XS(lrow + r + 8, s * 8 + c);
            unsigned a2 = XS(lrow + r,     s * 8 + c + 4);
            unsigned a3 = XS(lrow + r + 8, s * 8 + c + 4);
#pragma unroll
            for (int t = 0; t < 16; t++) {
                unsigned b0 = WS(t * 8 + r, s * 8 + c);
                unsigned b1 = WS(t * 8 + r, s * 8 + c + 4);
                mma_tf32(acc[t][0], acc[t][1], acc[t][2], acc[t][3],
                         a0, a1, a2, a3, b0, b1);
            }
        }
        __syncthreads();
    }

    const int row_a = m0 + lrow + r;
    const int row_b = row_a + 8;
#pragma unroll
    for (int t = 0; t < 16; t++) {
        int col0 = t * 8 + c * 2;
        float2 bias = *reinterpret_cast<const float2*>(&b[col0]);
        if (row_a < N_NODES) {
            *reinterpret_cast<float2*>(&g_hraw[(size_t)row_a * D + col0]) =
                make_float2(acc[t][0] + bias.x, acc[t][1] + bias.y);
        }
        if (row_b < N_NODES) {
            *reinterpret_cast<float2*>(&g_hraw[(size_t)row_b * D + col0]) =
                make_float2(acc[t][2] + bias.x, acc[t][3] + bias.y);
        }
    }
}

// ---------------- scale: h' = fp16( dis[row] * h_raw[row] ) -----------------
__global__ __launch_bounds__(256) void scale_kernel()
{
    int gid = blockIdx.x * 256 + threadIdx.x;   // N_NODES*16 threads
    int row = gid >> 4, q = gid & 15;
    if (row >= N_NODES) return;
    float dd = g_dis[row];
    const float4* src = reinterpret_cast<const float4*>(&g_hraw[(size_t)row * D + q * 8]);
    float4 f0 = src[0], f1 = src[1];
    __half2 h0 = __floats2half2_rn(dd * f0.x, dd * f0.y);
    __half2 h1 = __floats2half2_rn(dd * f0.z, dd * f0.w);
    __half2 h2 = __floats2half2_rn(dd * f1.x, dd * f1.y);
    __half2 h3 = __floats2half2_rn(dd * f1.z, dd * f1.w);
    uint4 u;
    u.x = *reinterpret_cast<unsigned*>(&h0);
    u.y = *reinterpret_cast<unsigned*>(&h1);
    u.z = *reinterpret_cast<unsigned*>(&h2);
    u.w = *reinterpret_cast<unsigned*>(&h3);
    reinterpret_cast<uint4*>(g_h)[(size_t)row * 16 + q] = u;
}

// ---------------- bucket fill: group src ids by dst -------------------------
__global__ __launch_bounds__(256) void fill_kernel(const int* __restrict__ ei)
{
    int e = blockIdx.x * 256 + threadIdx.x;
    if (e < N_EDGES) {
        int src = ei[e];
        int dst = ei[N_EDGES + e];
        int pos = atomicAdd(&g_cursor[dst], 1);
        g_bucket[pos] = src;
    }
}

// ---------------- gather v3: warp per node, full warp per edge (LDG.64) -----
// Lane owns bytes [lane*8, lane*8+8) of every 256B fp16 row. Every loop is
// warp-uniform; shfl broadcasts the edge's src id to all lanes.
#define ACC2(U) do {                                                          \
    float2 f_;                                                                \
    f_ = __half22float2(*reinterpret_cast<__half2*>(&(U).x)); a0.x += f_.x; a0.y += f_.y; \
    f_ = __half22float2(*reinterpret_cast<__half2*>(&(U).y)); a1.x += f_.x; a1.y += f_.y; \
} while (0)

__global__ __launch_bounds__(256) void gather_kernel(float* __restrict__ out)
{
    const int node = blockIdx.x * 8 + (threadIdx.x >> 5);
    if (node >= N_NODES) return;
    const int lane = threadIdx.x & 31;
    const unsigned FULL = 0xffffffffu;

    const int start = g_off[node];
    const int end   = g_off[node + 1];
    const int cnt   = end - start;
    const float dd  = g_dis[node];
    const uint2* hbase = reinterpret_cast<const uint2*>(g_h);   // row = 32 uint2

    // coalesced index prefetch: lane L holds src id of edge L
    int idx = (lane < cnt) ? g_bucket[start + lane] : 0;

    // self-loop piece
    float2 a0, a1;
    {
        uint2 u = hbase[(size_t)node * 32 + lane];
        a0 = __half22float2(*reinterpret_cast<__half2*>(&u.x));
        a1 = __half22float2(*reinterpret_cast<__half2*>(&u.y));
    }

    const int m = cnt < 32 ? cnt : 32;   // warp-uniform
    int base = 0;

    // 8 independent row loads in flight
    for (; base + 8 <= m; base += 8) {
        int s[8];
#pragma unroll
        for (int q = 0; q < 8; q++)
            s[q] = __shfl_sync(FULL, idx, base + q);
        uint2 u[8];
#pragma unroll
        for (int q = 0; q < 8; q++)
            u[q] = hbase[(size_t)s[q] * 32 + lane];
#pragma unroll
        for (int q = 0; q < 8; q++)
            ACC2(u[q]);
    }
    if (m - base >= 4) {
        int s[4];
#pragma unroll
        for (int q = 0; q < 4; q++)
            s[q] = __shfl_sync(FULL, idx, base + q);
        uint2 u[4];
#pragma unroll
        for (int q = 0; q < 4; q++)
            u[q] = hbase[(size_t)s[q] * 32 + lane];
#pragma unroll
        for (int q = 0; q < 4; q++)
            ACC2(u[q]);
        base += 4;
    }
    for (; base < m; base++) {           // warp-uniform, no predication
        int s0 = __shfl_sync(FULL, idx, base);
        uint2 u0 = hbase[(size_t)s0 * 32 + lane];
        ACC2(u0);
    }
    // rare tail: degree > 32 (uniform scalar load, broadcast to all lanes)
    for (int j = start + 32; j < end; j++) {
        int s0 = g_bucket[j];
        uint2 u0 = hbase[(size_t)s0 * 32 + lane];
        ACC2(u0);
    }

    const float coef = 0.125f;  // sqrt(2/128)
    float4 v;
    v.x = coef * fmaxf(dd * a0.x, 0.f);
    v.y = coef * fmaxf(dd * a0.y, 0.f);
    v.z = coef * fmaxf(dd * a1.x, 0.f);
    v.w = coef * fmaxf(dd * a1.y, 0.f);
    *reinterpret_cast<float4*>(&out[(size_t)node * D + lane * 4]) = v;
}

// ---------------- resources created before any harness checkpoint ----------
struct KLResources {
    cudaStream_t s2, s3;
    cudaEvent_t ev_fork, ev_hist, ev_dis, ev_csr, ev_join, ev_zero;
    KLResources() {
        cudaStreamCreateWithFlags(&s2, cudaStreamNonBlocking);
        cudaStreamCreateWithFlags(&s3, cudaStreamNonBlocking);
        cudaEventCreateWithFlags(&ev_fork, cudaEventDisableTiming);
        cudaEventCreateWithFlags(&ev_hist, cudaEventDisableTiming);
        cudaEventCreateWithFlags(&ev_dis,  cudaEventDisableTiming);
        cudaEventCreateWithFlags(&ev_csr,  cudaEventDisableTiming);
        cudaEventCreateWithFlags(&ev_join, cudaEventDisableTiming);
        cudaEventCreateWithFlags(&ev_zero, cudaEventDisableTiming);
        cudaFuncSetAttribute(gemm_mma_kernel,
                             cudaFuncAttributeMaxDynamicSharedMemorySize,
                             2 * 128 * 68 * 4);
    }
};
static KLResources g_res;

extern "C" void kernel_launch(void* const* d_in, const int* in_sizes, int n_in,
                              void* d_out, int out_size)
{
    const float* x  = (const float*)d_in[0];
    const int*   ei = (const int*)d_in[1];   // int32: JAX x64 disabled
    const float* W  = (const float*)d_in[2];
    const float* b  = (const float*)d_in[3];
    float* out = (float*)d_out;

    const int GEMM_SMEM = 2 * 128 * 68 * 4;  // 69632 B

    // fork: GEMM on s2 (depends on nothing)
    cudaEventRecord(g_res.ev_fork, 0);
    cudaStreamWaitEvent(g_res.s2, g_res.ev_fork, 0);
    cudaStreamWaitEvent(g_res.s3, g_res.ev_fork, 0);
    gemm_mma_kernel<<<(N_NODES + 127) / 128, 256, GEMM_SMEM, g_res.s2>>>(x, W, b);

    // main: hist -> scan -> fill   (g_cnt/g_deg are zero from previous call)
    hist_kernel<<<(N_EDGES + 255) / 256, 256>>>(ei);
    cudaEventRecord(g_res.ev_hist, 0);
    scan_p1<<<100, 256>>>();
    scan_p2<<<1, 128>>>();
    scan_p3<<<100, 256>>>();
    cudaEventRecord(g_res.ev_csr, 0);   // g_cnt no longer needed after this
    fill_kernel<<<(N_EDGES + 255) / 256, 256>>>(ei);

    // s3: dis after hist (parallel with scan/fill)
    cudaStreamWaitEvent(g_res.s3, g_res.ev_hist, 0);
    dis_kernel<<<(N_NODES + 255) / 256, 256, 0, g_res.s3>>>();
    cudaEventRecord(g_res.ev_dis, g_res.s3);

    // s2: scale after GEMM + dis; then trailing zero (after scan read g_cnt)
    cudaStreamWaitEvent(g_res.s2, g_res.ev_dis, 0);
    scale_kernel<<<(N_NODES * 16) / 256, 256, 0, g_res.s2>>>();
    cudaEventRecord(g_res.ev_join, g_res.s2);
    cudaStreamWaitEvent(g_res.s2, g_res.ev_csr, 0);
    zero_kernel<<<(N_PAD + 255) / 256, 256, 0, g_res.s2>>>();   // for next call
    cudaEventRecord(g_res.ev_zero, g_res.s2);

    // join: gather needs CSR (main) + h' (s2); zero overlaps with gather
    cudaStreamWaitEvent(0, g_res.ev_join, 0);
    gather_kernel<<<(N_NODES + 7) / 8, 256>>>(out);
    cudaStreamWaitEvent(0, g_res.ev_zero, 0);   // rejoin s2 fully before capture end
}